// round 3
// baseline (speedup 1.0000x reference)
#include <cuda_runtime.h>
#include <cstdint>

// Problem constants (fixed by the reference)
#define B_SZ    16384
#define S_GRID  7
#define CELLS_PER_B 49
#define CH      30
#define N_CELLS (B_SZ * CELLS_PER_B)   // 802816
#define TILE    256                    // cells per tile (== block threads)
#define N_TILES (N_CELLS / TILE)       // 3136 exactly
#define GRID_P  444                    // 148 SMs * 3 CTAs -> one persistent wave

#define CELL_PX 64.0f
#define IMG_PX  448.0f

// grid-wide state (reset by last-finishing block -> deterministic across replays)
__device__ float        g_acc;
__device__ unsigned int g_done;
__device__ unsigned int g_tile_ctr = GRID_P;   // tiles 0..GRID_P-1 are statically taken

__device__ __forceinline__ uint32_t smem_u32(const void* p) {
    uint32_t a;
    asm("{ .reg .u64 t; cvta.to.shared.u64 t, %1; cvt.u32.u64 %0, t; }"
        : "=r"(a) : "l"(p));
    return a;
}

__device__ __forceinline__ float4 decode_box(float p0, float p1, float p2, float p3,
                                             float gx, float gy) {
    float cx = p0 * CELL_PX + gx;
    float cy = p1 * CELL_PX + gy;
    float w  = p2 * IMG_PX;
    float h  = p3 * IMG_PX;
    float4 r;
    r.x = fminf(fmaxf(cx - w * 0.5f, 0.0f), IMG_PX);
    r.y = fminf(fmaxf(cy - h * 0.5f, 0.0f), IMG_PX);
    r.z = fminf(fmaxf(cx + w * 0.5f, 0.0f), IMG_PX);
    r.w = fminf(fmaxf(cy + h * 0.5f, 0.0f), IMG_PX);
    return r;
}

__device__ __forceinline__ float iou_fn(float4 a, float4 b) {
    float l  = fmaxf(a.x, b.x);
    float r  = fminf(a.z, b.z);
    float tt = fmaxf(a.y, b.y);
    float bo = fminf(a.w, b.w);
    bool m = (l < r) && (tt < bo);
    float inter = (r - l) * (bo - tt);
    float uni = (a.z - a.x) * (a.w - a.y) + (b.z - b.x) * (b.w - b.y);
    return m ? inter / (uni - inter) : 0.0f;
}

// Prefetch one tile's target slab (256 cells x 30 ch = 30720 B) into smem.
// Always commits a group (empty if !valid) to keep wait_group counting uniform.
__device__ __forceinline__ void prefetch_tile(float* dst, const float* __restrict__ tgt,
                                              unsigned t, bool valid) {
    if (valid) {
        const float4* src = reinterpret_cast<const float4*>(tgt + (size_t)t * (TILE * CH));
        uint32_t base = smem_u32(dst);
        #pragma unroll
        for (int k = 0; k < 8; k++) {
            int i = threadIdx.x + k * TILE;
            if (i < (TILE * CH) / 4) {
                asm volatile("cp.async.ca.shared.global [%0], [%1], 16;\n"
                             :: "r"(base + i * 16), "l"(src + i));
            }
        }
    }
    asm volatile("cp.async.commit_group;\n" ::: "memory");
}

__device__ __forceinline__ float compute_tile(const float* __restrict__ inp,
                                              const float x[CH],
                                              const float* __restrict__ t,
                                              float gx, float gy) {
    float4 pb1 = decode_box(x[0], x[1], x[2], x[3], gx, gy);
    float4 pb2 = decode_box(x[5], x[6], x[7], x[8], gx, gy);
    float4 tb1 = decode_box(t[0], t[1], t[2], t[3], gx, gy);
    float4 tb2 = decode_box(t[5], t[6], t[7], t[8], gx, gy);

    float iou1 = iou_fn(pb1, tb1);
    float iou2 = iou_fn(pb2, tb2);
    bool  mask = iou1 < iou2;
    float iou  = mask ? iou2 : iou1;

    float s0 = mask ? x[5] : x[0];
    float s1 = mask ? x[6] : x[1];
    float s2 = mask ? x[7] : x[2];
    float s3 = mask ? x[8] : x[3];
    float s4 = mask ? x[9] : x[4];

    float w = (t[4] == 1.0f) ? 1.0f : 0.0f;

    float d0 = s0 - t[0], d1 = s1 - t[1];
    float coord = d0 * d0 + d1 * d1;
    float e2 = sqrtf(s2) - sqrtf(t[2]);
    float e3 = sqrtf(s3) - sqrtf(t[3]);
    float size = e2 * e2 + e3 * e3;
    float dc = s4 - iou;
    float conf = dc * dc;
    float noobj = s4 * s4;

    float cls = 0.0f;
    #pragma unroll
    for (int c = 10; c < CH; c++) {
        float d = x[c] - t[c];
        cls += d * d;
    }

    return w * (5.0f * coord + 5.0f * size + conf + cls)
         + (1.0f - w) * 0.5f * noobj;
}

__global__ __launch_bounds__(TILE) void yolo_loss_kernel(
    const float* __restrict__ inp,   // [B, 30, 7, 7]
    const float* __restrict__ tgt,   // [B, 7, 7, 30] == [N_CELLS, 30]
    float* __restrict__ out)
{
    __shared__ float st[2][TILE * CH];     // double-buffered target slabs (2 x 30720 B)
    __shared__ float warp_sums[TILE / 32];
    __shared__ unsigned s_idx;

    // prologue: static first tile, fetch the following one from the counter
    unsigned t_cur = blockIdx.x;           // < GRID_P <= N_TILES
    if (threadIdx.x == 0) s_idx = atomicAdd(&g_tile_ctr, 1u);
    prefetch_tile(st[0], tgt, t_cur, true);
    __syncthreads();
    unsigned t_next = s_idx;

    float acc = 0.0f;
    int bufi = 0;

    while (t_cur < N_TILES) {
        // 1) prefetch t_next into the other buffer (its readers passed barrier B)
        prefetch_tile(st[bufi ^ 1], tgt, t_next, t_next < N_TILES);

        // 2) thread 0 fetches the index for the tile after t_next
        if (threadIdx.x == 0) s_idx = atomicAdd(&g_tile_ctr, 1u);

        // 3) issue all 30 input loads for t_cur while cp.async streams
        const int n    = (int)t_cur * TILE + threadIdx.x;
        const int b    = n / CELLS_PER_B;
        const int cell = n - b * CELLS_PER_B;
        const int row  = cell / S_GRID;
        const int col  = cell - row * S_GRID;
        const float gx = (float)col * CELL_PX;
        const float gy = (float)row * CELL_PX;

        const float* xb = inp + (size_t)b * (CH * CELLS_PER_B) + cell;
        float x[CH];
        #pragma unroll
        for (int c = 0; c < CH; c++)
            x[c] = __ldg(&xb[c * CELLS_PER_B]);

        // 4) barrier A: current tile's target slab is resident
        asm volatile("cp.async.wait_group 1;\n" ::: "memory");
        __syncthreads();

        const float* t = st[bufi] + threadIdx.x * CH;
        acc += compute_tile(inp, x, t, gx, gy);

        unsigned t_nn = s_idx;   // read after barrier A; rewritten only after barrier B

        // 5) barrier B: everyone done reading st[bufi] before it is refilled
        __syncthreads();

        t_cur = t_next;
        t_next = t_nn;
        bufi ^= 1;
    }

    // ---- block reduction (once per block) ----
    #pragma unroll
    for (int o = 16; o > 0; o >>= 1)
        acc += __shfl_down_sync(0xFFFFFFFFu, acc, o);

    const int lane = threadIdx.x & 31;
    const int wid  = threadIdx.x >> 5;
    if (lane == 0) warp_sums[wid] = acc;
    __syncthreads();

    if (threadIdx.x == 0) {
        float v = 0.0f;
        #pragma unroll
        for (int i = 0; i < TILE / 32; i++) v += warp_sums[i];

        atomicAdd(&g_acc, v);
        __threadfence();
        unsigned int done = atomicAdd(&g_done, 1u);
        if (done == GRID_P - 1) {
            out[0]     = g_acc;        // publish
            g_acc      = 0.0f;         // reset for next replay
            g_done     = 0u;
            g_tile_ctr = GRID_P;
        }
    }
}

extern "C" void kernel_launch(void* const* d_in, const int* in_sizes, int n_in,
                              void* d_out, int out_size) {
    const float* inp = (const float*)d_in[0];   // [16384, 30, 7, 7]
    const float* tgt = (const float*)d_in[1];   // [16384, 7, 7, 30]
    float* out = (float*)d_out;                 // scalar

    yolo_loss_kernel<<<GRID_P, TILE>>>(inp, tgt, out);
}